// round 2
// baseline (speedup 1.0000x reference)
#include <cuda_runtime.h>
#include <cstdint>
#include <cstddef>

// Problem constants
#define BT    4
#define NN    2048
#define FIN   512
#define FOUT  128
#define PIN   256
#define POUT  128
#define HEAD  4
#define KD    32           // per-head dim

// Scratch (device globals; no allocation allowed)
__device__ float g_x  [2*BT*NN*POUT];   // init linear output (residual source)
__device__ float g_xh [2*BT*NN*POUT];   // proj output (per-head features)
__device__ float g_G  [2*BT*NN*POUT];   // PPIGE output
__device__ float g_pqs[2*BT*NN*12];     // per row i, per head: {-s1, exp(s1), exp(.2 s1)}
__device__ float g_tuv[2*BT*NN*12];     // per col j, per head: {t, exp(t), exp(.2 t)},  t = s2 + attb
__device__ float g_hgge[2*BT*FOUT];
__device__ float g_gaga[2*BT*FOUT];

// ---------------------------------------------------------------------------
// Generic C[r][c] = sum_k A[r][k]*W[c][k] (+bias).  BM=64 rows, 128 cols, BK=16.
// mode 0: A = bio_{a,b} (per branch), C = g_x.   mode 1: A = g_x, C = g_xh.
// ---------------------------------------------------------------------------
__global__ __launch_bounds__(256) void gemm_tn(
    const float* __restrict__ A0, const float* __restrict__ A1,
    const float* __restrict__ W,  const float* __restrict__ bias,
    int Kdim, int mode)
{
    __shared__ float As[16][65];
    __shared__ float Ws[16][128];

    const int branch = blockIdx.y;
    const float* Ain;
    float* Cout;
    if (mode == 0) { Ain = branch ? A1 : A0;                      Cout = g_x;  }
    else           { Ain = g_x + (size_t)branch * BT*NN*POUT;     Cout = g_xh; }
    Cout += (size_t)branch * BT*NN*POUT;

    const int row0 = blockIdx.x * 64;
    const int tid  = threadIdx.x;
    const int tx   = tid & 31;      // col group (4 cols)
    const int ty   = tid >> 5;      // row group (8 rows)

    float acc[8][4];
#pragma unroll
    for (int i = 0; i < 8; i++)
#pragma unroll
        for (int j = 0; j < 4; j++) acc[i][j] = 0.f;

    for (int k0 = 0; k0 < Kdim; k0 += 16) {
        {   // A tile: 64x16
            int r = tid >> 2, kq = tid & 3;
            float4 v = *(const float4*)&Ain[(size_t)(row0 + r)*Kdim + k0 + kq*4];
            As[kq*4+0][r] = v.x; As[kq*4+1][r] = v.y;
            As[kq*4+2][r] = v.z; As[kq*4+3][r] = v.w;
        }
        {   // W tile: 128x16
            int c = tid >> 1, kh = tid & 1;
#pragma unroll
            for (int p = 0; p < 2; p++) {
                int kk = kh*8 + p*4;
                float4 v = *(const float4*)&W[(size_t)c*Kdim + k0 + kk];
                Ws[kk+0][c] = v.x; Ws[kk+1][c] = v.y;
                Ws[kk+2][c] = v.z; Ws[kk+3][c] = v.w;
            }
        }
        __syncthreads();
#pragma unroll
        for (int k = 0; k < 16; k++) {
            float4 wv = *(const float4*)&Ws[k][tx*4];
            float av[8];
#pragma unroll
            for (int i = 0; i < 8; i++) av[i] = As[k][ty*8 + i];
#pragma unroll
            for (int i = 0; i < 8; i++) {
                acc[i][0] += av[i]*wv.x; acc[i][1] += av[i]*wv.y;
                acc[i][2] += av[i]*wv.z; acc[i][3] += av[i]*wv.w;
            }
        }
        __syncthreads();
    }
    float4 bv = make_float4(0.f, 0.f, 0.f, 0.f);
    if (bias) bv = *(const float4*)&bias[tx*4];
#pragma unroll
    for (int i = 0; i < 8; i++) {
        float4 o = make_float4(acc[i][0]+bv.x, acc[i][1]+bv.y,
                               acc[i][2]+bv.z, acc[i][3]+bv.w);
        *(float4*)&Cout[(size_t)(row0 + ty*8 + i)*POUT + tx*4] = o;
    }
}

// ---------------------------------------------------------------------------
// Per-row attention scalars: s1,s2 per head -> factored exp terms.
// ---------------------------------------------------------------------------
__global__ __launch_bounds__(256) void s_kernel(
    const float* __restrict__ attw, const float* __restrict__ attb)
{
    const int warp = threadIdx.x >> 5, lane = threadIdx.x & 31;
    const size_t row = (size_t)blockIdx.x * 8 + warp;   // 0 .. 2*BT*NN-1
    const float* xr = g_xh + row * POUT;
#pragma unroll
    for (int h = 0; h < HEAD; h++) {
        float xv = xr[h*KD + lane];
        float s1 = xv * attw[h*2*KD + lane];
        float s2 = xv * attw[h*2*KD + KD + lane];
#pragma unroll
        for (int off = 16; off; off >>= 1) {
            s1 += __shfl_xor_sync(0xffffffffu, s1, off);
            s2 += __shfl_xor_sync(0xffffffffu, s2, off);
        }
        if (lane == 0) {
            float t = s2 + attb[h];
            g_pqs[row*12 + h*3 + 0] = -s1;
            g_pqs[row*12 + h*3 + 1] = __expf(s1);
            g_pqs[row*12 + h*3 + 2] = __expf(0.2f*s1);
            g_tuv[row*12 + h*3 + 0] = t;
            g_tuv[row*12 + h*3 + 1] = __expf(t);
            g_tuv[row*12 + h*3 + 2] = __expf(0.2f*t);
        }
    }
}

// ---------------------------------------------------------------------------
// GAT attention + relu + residual.  Warp per output row; ballot-compressed
// adjacency; factored scores (no transcendental in the N^2 loop).
// Lane = (h = lane>>3, kq = lane&7) owning 4 output dims.
// ---------------------------------------------------------------------------
__global__ __launch_bounds__(1024, 1) void attn_kernel(
    const int* __restrict__ A0, const int* __restrict__ A1)
{
    __shared__ float xh_s[64 * 132];   // [j][h*33 + k], conflict-free reads
    __shared__ float tuv_s[64 * 12];

    const int branch = blockIdx.z, b = blockIdx.y;
    const int warp = threadIdx.x >> 5, lane = threadIdx.x & 31;
    const int i = blockIdx.x * 32 + warp;
    const int h  = lane >> 3, kq = lane & 7;
    const int h3 = h * 3;
    const int hk = h * 33 + kq * 4;

    const size_t rbase = (size_t)(branch*BT + b) * NN;
    const size_t row   = rbase + i;
    const float negS1 = g_pqs[row*12 + h3 + 0];
    const float P     = g_pqs[row*12 + h3 + 1];
    const float Q     = g_pqs[row*12 + h3 + 2];
    const int* Ap = (branch ? A1 : A0) + ((size_t)b*NN + i) * NN;

    const float* xhb = g_xh + rbase * POUT;
    const float* tvb = g_tuv + rbase * 12;

    float acc0 = 0.f, acc1 = 0.f, acc2 = 0.f, acc3 = 0.f, denom = 0.f;

    for (int jt = 0; jt < NN; jt += 64) {
        __syncthreads();
        {   // stage tiles
            int t = threadIdx.x;
#pragma unroll
            for (int p = 0; p < 2; p++) {
                int f4 = t + p*1024;
                int r = f4 >> 5, c4 = f4 & 31;
                float4 v = *(const float4*)&xhb[(size_t)(jt + r)*POUT + c4*4];
                int off = r*132 + (c4 >> 3)*33 + (c4 & 7)*4;
                xh_s[off+0] = v.x; xh_s[off+1] = v.y;
                xh_s[off+2] = v.z; xh_s[off+3] = v.w;
            }
            if (t < 768) tuv_s[t] = tvb[(size_t)jt*12 + t];
        }
        __syncthreads();
#pragma unroll
        for (int c = 0; c < 2; c++) {
            int av = Ap[jt + c*32 + lane];
            unsigned m = __ballot_sync(0xffffffffu, av != 0);
            const int cb = c * 32;
            while (m) {
                int jj = __ffs(m) - 1;
                m &= m - 1;
                int jr = cb + jj;
                const float* tp = &tuv_s[jr*12 + h3];
                float tt = tp[0];
                float e = (tt >= negS1) ? (P * tp[1]) : (Q * tp[2]);
                denom += e;
                const float* xp = &xh_s[jr*132 + hk];
                acc0 += e * xp[0]; acc1 += e * xp[1];
                acc2 += e * xp[2]; acc3 += e * xp[3];
            }
        }
    }
    float inv = 1.f / fmaxf(denom, 1e-30f);
    const float4 xr = *(const float4*)&g_x[row*POUT + h*KD + kq*4];
    float4 o;
    o.x = fmaxf(acc0*inv, 0.f) + xr.x;
    o.y = fmaxf(acc1*inv, 0.f) + xr.y;
    o.z = fmaxf(acc2*inv, 0.f) + xr.z;
    o.w = fmaxf(acc3*inv, 0.f) + xr.w;
    *(float4*)&g_G[row*POUT + h*KD + kq*4] = o;
}

// ---------------------------------------------------------------------------
// GGE: h = relu(relu(a@W1^T+b1)@W2^T+b2).  Tiny.
// ---------------------------------------------------------------------------
__global__ __launch_bounds__(128) void gge_kernel(
    const float* __restrict__ a, const float* __restrict__ b,
    const float* __restrict__ W1, const float* __restrict__ b1,
    const float* __restrict__ W2, const float* __restrict__ b2)
{
    __shared__ float in_s[FIN];
    __shared__ float h1[128];
    const int bi = blockIdx.x, branch = blockIdx.y;
    const float* in = (branch ? b : a) + bi*FIN;
    const int tid = threadIdx.x;
    for (int k = tid; k < FIN; k += 128) in_s[k] = in[k];
    __syncthreads();
    float acc = b1[tid];
#pragma unroll 8
    for (int k = 0; k < FIN; k++) acc += in_s[k] * W1[(size_t)tid*FIN + k];
    h1[tid] = fmaxf(acc, 0.f);
    __syncthreads();
    float acc2 = b2[tid];
#pragma unroll 8
    for (int k = 0; k < 128; k++) acc2 += h1[k] * W2[tid*128 + k];
    g_hgge[(branch*BT + bi)*FOUT + tid] = fmaxf(acc2, 0.f);
}

// ---------------------------------------------------------------------------
// GAGA pooling: softmax(G.h) weighted sum of G over N.
// ---------------------------------------------------------------------------
__global__ __launch_bounds__(256) void gaga_kernel()
{
    __shared__ float hv[128];
    __shared__ float sc[NN];
    __shared__ float red[256];
    const int bi = blockIdx.x, branch = blockIdx.y;
    const int base = branch*BT + bi;
    const float* Gp = g_G + (size_t)base * NN * POUT;
    const int tid = threadIdx.x;
    if (tid < 128) hv[tid] = g_hgge[base*FOUT + tid];
    __syncthreads();

    float lmax = -1e30f;
    for (int n = tid; n < NN; n += 256) {
        float acc = 0.f;
#pragma unroll 8
        for (int d = 0; d < 128; d++) acc += Gp[(size_t)n*POUT + d] * hv[d];
        sc[n] = acc;
        lmax = fmaxf(lmax, acc);
    }
    red[tid] = lmax; __syncthreads();
    for (int s = 128; s; s >>= 1) {
        if (tid < s) red[tid] = fmaxf(red[tid], red[tid+s]);
        __syncthreads();
    }
    float mx = red[0]; __syncthreads();

    float lsum = 0.f;
    for (int n = tid; n < NN; n += 256) {
        float e = __expf(sc[n] - mx);
        sc[n] = e;
        lsum += e;
    }
    red[tid] = lsum; __syncthreads();
    for (int s = 128; s; s >>= 1) {
        if (tid < s) red[tid] += red[tid+s];
        __syncthreads();
    }
    float winv = 1.f / red[0]; __syncthreads();

    const int half = tid >> 7, d = tid & 127;
    float acc = 0.f;
    const int n0 = half * (NN/2);
    for (int n = n0; n < n0 + NN/2; n++) acc += Gp[(size_t)n*POUT + d] * sc[n];
    red[tid] = acc; __syncthreads();
    if (tid < 128) g_gaga[base*FOUT + tid] = (red[tid] + red[tid+128]) * winv;
}

// ---------------------------------------------------------------------------
// LED head + log_softmax -> out[4][2]
// ---------------------------------------------------------------------------
__global__ __launch_bounds__(256) void led_kernel(
    const float* __restrict__ convW, const float* __restrict__ convb,
    const float* __restrict__ W1, const float* __restrict__ b1,
    const float* __restrict__ W2, const float* __restrict__ b2,
    float* __restrict__ out)
{
    __shared__ float ea[256], eb[256], cat[512], hx[128], lg[2];
    const int tid = threadIdx.x;
    for (int bt = 0; bt < BT; bt++) {
        __syncthreads();
        if (tid < 128) {
            ea[tid]     = g_hgge[(0*BT + bt)*FOUT + tid];
            ea[128+tid] = g_gaga[(0*BT + bt)*FOUT + tid];
            eb[tid]     = g_hgge[(1*BT + bt)*FOUT + tid];
            eb[128+tid] = g_gaga[(1*BT + bt)*FOUT + tid];
        }
        __syncthreads();
        {
            float va = convb[tid], vb = convb[tid];
#pragma unroll 8
            for (int k = 0; k < 256; k++) {
                float w = convW[(size_t)tid*256 + k];
                va += ea[k]*w; vb += eb[k]*w;
            }
            cat[tid]       = fmaxf(va, vb);
            cat[256 + tid] = ea[tid] - eb[tid];
        }
        __syncthreads();
        if (tid < 128) {
            float acc = b1[tid];
#pragma unroll 8
            for (int k = 0; k < 512; k++) acc += cat[k] * W1[(size_t)tid*512 + k];
            hx[tid] = fmaxf(acc, 0.f);
        }
        __syncthreads();
        if (tid < 2) {
            float l = b2[tid];
#pragma unroll 8
            for (int k = 0; k < 128; k++) l += hx[k] * W2[tid*128 + k];
            lg[tid] = l;
        }
        __syncthreads();
        if (tid == 0) {
            float m = fmaxf(lg[0], lg[1]);
            float lse = m + logf(__expf(lg[0]-m) + __expf(lg[1]-m));
            out[bt*2 + 0] = lg[0] - lse;
            out[bt*2 + 1] = lg[1] - lse;
        }
    }
}

// ---------------------------------------------------------------------------
extern "C" void kernel_launch(void* const* d_in, const int* in_sizes, int n_in,
                              void* d_out, int out_size)
{
    const float* a      = (const float*)d_in[0];
    const float* bio_a  = (const float*)d_in[1];
    const int*   Aadj   = (const int*)  d_in[2];
    const float* b      = (const float*)d_in[3];
    const float* bio_b  = (const float*)d_in[4];
    const int*   Badj   = (const int*)  d_in[5];
    const float* initW  = (const float*)d_in[6];
    const float* initb  = (const float*)d_in[7];
    const float* projW  = (const float*)d_in[8];
    const float* attw   = (const float*)d_in[9];
    const float* attb   = (const float*)d_in[10];
    const float* ggeW1  = (const float*)d_in[11];
    const float* ggeb1  = (const float*)d_in[12];
    const float* ggeW2  = (const float*)d_in[13];
    const float* ggeb2  = (const float*)d_in[14];
    const float* convW  = (const float*)d_in[15];
    const float* convb  = (const float*)d_in[16];
    const float* ledW1  = (const float*)d_in[17];
    const float* ledb1  = (const float*)d_in[18];
    const float* ledW2  = (const float*)d_in[19];
    const float* ledb2  = (const float*)d_in[20];
    float* out = (float*)d_out;

    // x = bio @ initW^T + initb          (both branches)
    gemm_tn<<<dim3(BT*NN/64, 2), 256>>>(bio_a, bio_b, initW, initb, PIN, 0);
    // xh = x @ projW^T
    gemm_tn<<<dim3(BT*NN/64, 2), 256>>>(nullptr, nullptr, projW, nullptr, POUT, 1);
    // attention scalar precompute
    s_kernel<<<2*BT*NN/8, 256>>>(attw, attb);
    // GGE (independent)
    gge_kernel<<<dim3(BT, 2), 128>>>(a, b, ggeW1, ggeb1, ggeW2, ggeb2);
    // GAT attention + residual -> G
    attn_kernel<<<dim3(NN/32, BT, 2), 1024>>>(Aadj, Badj);
    // GAGA pooling
    gaga_kernel<<<dim3(BT, 2), 256>>>();
    // LED head + log_softmax
    led_kernel<<<1, 256>>>(convW, convb, ledW1, ledb1, ledW2, ledb2, out);
}

// round 3
// speedup vs baseline: 2.0258x; 2.0258x over previous
#include <cuda_runtime.h>
#include <cstdint>
#include <cstddef>

// Problem constants
#define BT    4
#define NN    2048
#define FIN   512
#define FOUT  128
#define PIN   256
#define POUT  128
#define HEAD  4
#define KD    32           // per-head dim

// Scratch (device globals; no allocation allowed)
__device__ float g_x   [2*BT*NN*POUT];   // init linear output (residual source)
__device__ float g_xh  [2*BT*NN*POUT];   // proj output (per-head features)
__device__ float g_G   [2*BT*NN*POUT];   // PPIGE output
__device__ float g_pqs4[2*BT*NN*16];     // per row i, head h: {-s1, e^{s1}, e^{.2 s1}, 0}
__device__ float g_tuv4[2*BT*NN*16];     // per col j, head h: {t, e^{t}, e^{.2 t}, 0}
__device__ float g_hgge[2*BT*FOUT];

// ---------------------------------------------------------------------------
// C[r][c] = sum_k A[r][k]*W[c][k] (+bias).  BM=64, 128 cols, BK=16.
// mode 0: A = bio_{a,b}, C = g_x.
// mode 1: A = g_x, C = g_xh, fused epilogue computes attention scalars.
// ---------------------------------------------------------------------------
__global__ __launch_bounds__(256) void gemm_tn(
    const float* __restrict__ A0, const float* __restrict__ A1,
    const float* __restrict__ W,  const float* __restrict__ bias,
    const float* __restrict__ attw, const float* __restrict__ attb,
    int Kdim, int mode)
{
    __shared__ float As[16][65];
    __shared__ float Ws[16][128];

    const int branch = blockIdx.y;
    const float* Ain;
    float* Cout;
    if (mode == 0) { Ain = branch ? A1 : A0;                   Cout = g_x;  }
    else           { Ain = g_x + (size_t)branch * BT*NN*POUT;  Cout = g_xh; }
    Cout += (size_t)branch * BT*NN*POUT;

    const int row0 = blockIdx.x * 64;
    const int tid  = threadIdx.x;
    const int tx   = tid & 31;      // lane: col group (4 cols)
    const int ty   = tid >> 5;      // warp: row group (8 rows)

    float acc[8][4];
#pragma unroll
    for (int i = 0; i < 8; i++)
#pragma unroll
        for (int j = 0; j < 4; j++) acc[i][j] = 0.f;

    for (int k0 = 0; k0 < Kdim; k0 += 16) {
        {   // A tile: 64x16
            int r = tid >> 2, kq = tid & 3;
            float4 v = *(const float4*)&Ain[(size_t)(row0 + r)*Kdim + k0 + kq*4];
            As[kq*4+0][r] = v.x; As[kq*4+1][r] = v.y;
            As[kq*4+2][r] = v.z; As[kq*4+3][r] = v.w;
        }
        {   // W tile: 128x16
            int c = tid >> 1, kh = tid & 1;
#pragma unroll
            for (int p = 0; p < 2; p++) {
                int kk = kh*8 + p*4;
                float4 v = *(const float4*)&W[(size_t)c*Kdim + k0 + kk];
                Ws[kk+0][c] = v.x; Ws[kk+1][c] = v.y;
                Ws[kk+2][c] = v.z; Ws[kk+3][c] = v.w;
            }
        }
        __syncthreads();
#pragma unroll
        for (int k = 0; k < 16; k++) {
            float4 wv = *(const float4*)&Ws[k][tx*4];
            float av[8];
#pragma unroll
            for (int i = 0; i < 8; i++) av[i] = As[k][ty*8 + i];
#pragma unroll
            for (int i = 0; i < 8; i++) {
                acc[i][0] += av[i]*wv.x; acc[i][1] += av[i]*wv.y;
                acc[i][2] += av[i]*wv.z; acc[i][3] += av[i]*wv.w;
            }
        }
        __syncthreads();
    }
    float4 bv = make_float4(0.f, 0.f, 0.f, 0.f);
    if (bias) bv = *(const float4*)&bias[tx*4];
#pragma unroll
    for (int i = 0; i < 8; i++) {
        float4 o = make_float4(acc[i][0]+bv.x, acc[i][1]+bv.y,
                               acc[i][2]+bv.z, acc[i][3]+bv.w);
        *(float4*)&Cout[(size_t)(row0 + ty*8 + i)*POUT + tx*4] = o;
    }

    if (mode == 1) {
        // Fused attention-scalar epilogue. cols owned by this lane all lie in
        // head h = tx>>3; local col = (tx&7)*4 + q.
        const int h = tx >> 3, lq = tx & 7;
        float w1[4], w2[4];
#pragma unroll
        for (int q = 0; q < 4; q++) {
            w1[q] = attw[h*2*KD + lq*4 + q];
            w2[q] = attw[h*2*KD + KD + lq*4 + q];
        }
        const float bb = attb[h];
#pragma unroll
        for (int i = 0; i < 8; i++) {
            float p1 = acc[i][0]*w1[0] + acc[i][1]*w1[1]
                     + acc[i][2]*w1[2] + acc[i][3]*w1[3];
            float p2 = acc[i][0]*w2[0] + acc[i][1]*w2[1]
                     + acc[i][2]*w2[2] + acc[i][3]*w2[3];
#pragma unroll
            for (int off = 1; off < 8; off <<= 1) {
                p1 += __shfl_xor_sync(0xffffffffu, p1, off);
                p2 += __shfl_xor_sync(0xffffffffu, p2, off);
            }
            if (lq == 0) {
                size_t r = (size_t)branch*BT*NN + row0 + ty*8 + i;
                float s1 = p1, t = p2 + bb;
                float* pq = &g_pqs4[r*16 + h*4];
                pq[0] = -s1;
                pq[1] = __expf(s1);
                pq[2] = __expf(0.2f*s1);
                float* tv = &g_tuv4[r*16 + h*4];
                tv[0] = t;
                tv[1] = __expf(t);
                tv[2] = __expf(0.2f*t);
            }
        }
    }
}

// ---------------------------------------------------------------------------
// GGE: h = relu(relu(a@W1^T+b1)@W2^T+b2).  Warp-per-output, coalesced.
// ---------------------------------------------------------------------------
__global__ __launch_bounds__(512) void gge_kernel(
    const float* __restrict__ a, const float* __restrict__ b,
    const float* __restrict__ W1, const float* __restrict__ b1,
    const float* __restrict__ W2, const float* __restrict__ b2)
{
    __shared__ float in_s[FIN];
    __shared__ float h1[128];
    const int bi = blockIdx.x, branch = blockIdx.y;
    const float* in = (branch ? b : a) + bi*FIN;
    const int tid = threadIdx.x, warp = tid >> 5, lane = tid & 31;
    if (tid < FIN) in_s[tid] = in[tid];
    __syncthreads();
#pragma unroll
    for (int o = warp; o < 128; o += 16) {
        float acc = 0.f;
#pragma unroll
        for (int k = lane; k < FIN; k += 32) acc += in_s[k] * W1[(size_t)o*FIN + k];
#pragma unroll
        for (int off = 16; off; off >>= 1) acc += __shfl_xor_sync(0xffffffffu, acc, off);
        if (lane == 0) h1[o] = fmaxf(acc + b1[o], 0.f);
    }
    __syncthreads();
#pragma unroll
    for (int o = warp; o < 128; o += 16) {
        float acc = 0.f;
#pragma unroll
        for (int k = lane; k < 128; k += 32) acc += h1[k] * W2[o*128 + k];
#pragma unroll
        for (int off = 16; off; off >>= 1) acc += __shfl_xor_sync(0xffffffffu, acc, off);
        if (lane == 0) g_hgge[(branch*BT + bi)*FOUT + o] = fmaxf(acc + b2[o], 0.f);
    }
}

// ---------------------------------------------------------------------------
// GAT attention + relu + residual.  Warp per output row; ballot-compressed
// adjacency; factored scores.  Per-j data interleaved in one smem row:
// sm[j][0:128] = xh, sm[j][128+h*4] = {t, e^t, e^{0.2t}, pad}.
// Lane owns cols lane*4..lane*4+3 (head h = lane>>3).
// ---------------------------------------------------------------------------
__global__ __launch_bounds__(1024, 2) void attn_kernel(
    const int* __restrict__ A0, const int* __restrict__ A1)
{
    __shared__ float sm[64 * 144];

    const int branch = blockIdx.z, b = blockIdx.y;
    const int warp = threadIdx.x >> 5, lane = threadIdx.x & 31;
    const int i = blockIdx.x * 32 + warp;
    const int h  = lane >> 3;

    const size_t rbase = (size_t)(branch*BT + b) * NN;
    const size_t row   = rbase + i;
    const float4 pq = *(const float4*)&g_pqs4[row*16 + h*4];  // {-s1, P, Q, pad}
    const int* Ap = (branch ? A1 : A0) + ((size_t)b*NN + i) * NN;

    const float* xhb = g_xh + rbase * POUT;
    const float* tvb = g_tuv4 + rbase * 16;

    float acc0 = 0.f, acc1 = 0.f, acc2 = 0.f, acc3 = 0.f, den = 0.f;

    for (int jt = 0; jt < NN; jt += 64) {
        __syncthreads();
        {   // stage 64 j-rows: xh (2048 float4) + tuv (256 float4)
            int t = threadIdx.x;
#pragma unroll
            for (int p = 0; p < 2; p++) {
                int f4 = t + p*1024;
                int r = f4 >> 5, c = f4 & 31;
                float4 v = *(const float4*)&xhb[(size_t)(jt + r)*POUT + c*4];
                *(float4*)&sm[r*144 + c*4] = v;
            }
            if (t < 256) {
                int r = t >> 2, c = t & 3;
                float4 v = *(const float4*)&tvb[(size_t)(jt + r)*16 + c*4];
                *(float4*)&sm[r*144 + 128 + c*4] = v;
            }
        }
        __syncthreads();

        int av0 = Ap[jt + lane];
        int av1 = Ap[jt + 32 + lane];
        unsigned m0 = __ballot_sync(0xffffffffu, av0 != 0);
        unsigned m1 = __ballot_sync(0xffffffffu, av1 != 0);

        const float* b0 = sm;
        while (m0) {
            int jj = __ffs(m0) - 1;
            m0 &= m0 - 1;
            const float* pj = b0 + jj*144;
            float4 tv = *(const float4*)(pj + 128 + h*4);
            float4 xv = *(const float4*)(pj + lane*4);
            float e = (tv.x >= pq.x) ? (pq.y * tv.y) : (pq.z * tv.z);
            den  += e;
            acc0 += e*xv.x; acc1 += e*xv.y; acc2 += e*xv.z; acc3 += e*xv.w;
        }
        const float* b1p = sm + 32*144;
        while (m1) {
            int jj = __ffs(m1) - 1;
            m1 &= m1 - 1;
            const float* pj = b1p + jj*144;
            float4 tv = *(const float4*)(pj + 128 + h*4);
            float4 xv = *(const float4*)(pj + lane*4);
            float e = (tv.x >= pq.x) ? (pq.y * tv.y) : (pq.z * tv.z);
            den  += e;
            acc0 += e*xv.x; acc1 += e*xv.y; acc2 += e*xv.z; acc3 += e*xv.w;
        }
    }
    float inv = 1.f / fmaxf(den, 1e-30f);
    const float4 xr = *(const float4*)&g_x[row*POUT + lane*4];
    float4 o;
    o.x = fmaxf(acc0*inv, 0.f) + xr.x;
    o.y = fmaxf(acc1*inv, 0.f) + xr.y;
    o.z = fmaxf(acc2*inv, 0.f) + xr.z;
    o.w = fmaxf(acc3*inv, 0.f) + xr.w;
    *(float4*)&g_G[row*POUT + lane*4] = o;
}

// ---------------------------------------------------------------------------
// GAGA pooling (both branches) + LED head + log_softmax.  One block per bt.
// ---------------------------------------------------------------------------
__global__ __launch_bounds__(1024) void gagaled_kernel(
    const float* __restrict__ convW, const float* __restrict__ convb,
    const float* __restrict__ W1, const float* __restrict__ b1,
    const float* __restrict__ W2, const float* __restrict__ b2,
    float* __restrict__ out)
{
    __shared__ float hv[2][128];
    __shared__ float pool[2][128];
    __shared__ float sc[NN];
    __shared__ float red[1024];
    __shared__ float cat[512];
    __shared__ float hx[128];

    const int bt = blockIdx.x;
    const int tid = threadIdx.x, warp = tid >> 5, lane = tid & 31;

    if (tid < 256) hv[tid >> 7][tid & 127] = g_hgge[((tid >> 7)*BT + bt)*FOUT + (tid & 127)];

    for (int br = 0; br < 2; br++) {
        const float* Gp = g_G + (size_t)(br*BT + bt) * NN * POUT;
        __syncthreads();
        // scores: warp per row
        for (int r = warp; r < NN; r += 32) {
            float4 g = *(const float4*)&Gp[(size_t)r*POUT + lane*4];
            float a = g.x*hv[br][lane*4+0] + g.y*hv[br][lane*4+1]
                    + g.z*hv[br][lane*4+2] + g.w*hv[br][lane*4+3];
#pragma unroll
            for (int off = 16; off; off >>= 1) a += __shfl_xor_sync(0xffffffffu, a, off);
            if (lane == 0) sc[r] = a;
        }
        __syncthreads();
        // block max
        float lm = -1e30f;
        for (int n = tid; n < NN; n += 1024) lm = fmaxf(lm, sc[n]);
        red[tid] = lm; __syncthreads();
        for (int s = 512; s; s >>= 1) {
            if (tid < s) red[tid] = fmaxf(red[tid], red[tid+s]);
            __syncthreads();
        }
        float mx = red[0]; __syncthreads();
        // exp + sum
        float ls = 0.f;
        for (int n = tid; n < NN; n += 1024) {
            float e = __expf(sc[n] - mx);
            sc[n] = e;
            ls += e;
        }
        red[tid] = ls; __syncthreads();
        for (int s = 512; s; s >>= 1) {
            if (tid < s) red[tid] += red[tid+s];
            __syncthreads();
        }
        float winv = 1.f / red[0]; __syncthreads();
        // weighted sum: 8 segments of 256 rows, thread (seg, d)
        const int seg = tid >> 7, d = tid & 127;
        float acc = 0.f;
        const int n0 = seg * 256;
#pragma unroll 8
        for (int n = n0; n < n0 + 256; n++) acc += Gp[(size_t)n*POUT + d] * sc[n];
        red[tid] = acc; __syncthreads();
        if (tid < 128) {
            float s = 0.f;
#pragma unroll
            for (int g = 0; g < 8; g++) s += red[g*128 + d];
            pool[br][d] = s * winv;
        }
    }
    __syncthreads();
    // ea = [h_a, pool_a], eb = [h_b, pool_b]; conv, maxpool, concat diff
    // cat[0:256] = max(ea@convW^T, eb@convW^T) + convb ; cat[256:512] = ea-eb
    for (int o = warp; o < 256; o += 32) {
        float va = 0.f, vb = 0.f;
#pragma unroll
        for (int k = lane; k < 256; k += 32) {
            float w  = convW[(size_t)o*256 + k];
            float eav = (k < 128) ? hv[0][k] : pool[0][k-128];
            float ebv = (k < 128) ? hv[1][k] : pool[1][k-128];
            va += eav * w; vb += ebv * w;
        }
#pragma unroll
        for (int off = 16; off; off >>= 1) {
            va += __shfl_xor_sync(0xffffffffu, va, off);
            vb += __shfl_xor_sync(0xffffffffu, vb, off);
        }
        if (lane == 0) cat[o] = fmaxf(va, vb) + convb[o];
    }
    if (tid < 256) {
        float eav = (tid < 128) ? hv[0][tid] : pool[0][tid-128];
        float ebv = (tid < 128) ? hv[1][tid] : pool[1][tid-128];
        cat[256 + tid] = eav - ebv;
    }
    __syncthreads();
    for (int o = warp; o < 128; o += 32) {
        float acc = 0.f;
#pragma unroll
        for (int k = lane; k < 512; k += 32) acc += cat[k] * W1[(size_t)o*512 + k];
#pragma unroll
        for (int off = 16; off; off >>= 1) acc += __shfl_xor_sync(0xffffffffu, acc, off);
        if (lane == 0) hx[o] = fmaxf(acc + b1[o], 0.f);
    }
    __syncthreads();
    if (warp < 2) {
        float acc = 0.f;
#pragma unroll
        for (int k = lane; k < 128; k += 32) acc += hx[k] * W2[warp*128 + k];
#pragma unroll
        for (int off = 16; off; off >>= 1) acc += __shfl_xor_sync(0xffffffffu, acc, off);
        if (lane == 0) red[warp] = acc + b2[warp];
    }
    __syncthreads();
    if (tid == 0) {
        float l0 = red[0], l1 = red[1];
        float m = fmaxf(l0, l1);
        float lse = m + logf(__expf(l0-m) + __expf(l1-m));
        out[bt*2 + 0] = l0 - lse;
        out[bt*2 + 1] = l1 - lse;
    }
}

// ---------------------------------------------------------------------------
extern "C" void kernel_launch(void* const* d_in, const int* in_sizes, int n_in,
                              void* d_out, int out_size)
{
    const float* a      = (const float*)d_in[0];
    const float* bio_a  = (const float*)d_in[1];
    const int*   Aadj   = (const int*)  d_in[2];
    const float* b      = (const float*)d_in[3];
    const float* bio_b  = (const float*)d_in[4];
    const int*   Badj   = (const int*)  d_in[5];
    const float* initW  = (const float*)d_in[6];
    const float* initb  = (const float*)d_in[7];
    const float* projW  = (const float*)d_in[8];
    const float* attw   = (const float*)d_in[9];
    const float* attb   = (const float*)d_in[10];
    const float* ggeW1  = (const float*)d_in[11];
    const float* ggeb1  = (const float*)d_in[12];
    const float* ggeW2  = (const float*)d_in[13];
    const float* ggeb2  = (const float*)d_in[14];
    const float* convW  = (const float*)d_in[15];
    const float* convb  = (const float*)d_in[16];
    const float* ledW1  = (const float*)d_in[17];
    const float* ledb1  = (const float*)d_in[18];
    const float* ledW2  = (const float*)d_in[19];
    const float* ledb2  = (const float*)d_in[20];
    float* out = (float*)d_out;

    // 1) x = bio @ initW^T + initb
    gemm_tn<<<dim3(BT*NN/64, 2), 256>>>(bio_a, bio_b, initW, initb,
                                        nullptr, nullptr, PIN, 0);
    // 2) xh = x @ projW^T  (+ fused attention-scalar epilogue)
    gemm_tn<<<dim3(BT*NN/64, 2), 256>>>(nullptr, nullptr, projW, nullptr,
                                        attw, attb, POUT, 1);
    // 3) GGE (independent)
    gge_kernel<<<dim3(BT, 2), 512>>>(a, b, ggeW1, ggeb1, ggeW2, ggeb2);
    // 4) GAT attention + residual -> G
    attn_kernel<<<dim3(NN/32, BT, 2), 1024>>>(Aadj, Badj);
    // 5) GAGA pooling + LED head + log_softmax
    gagaled_kernel<<<BT, 1024>>>(convW, convb, ledW1, ledb1, ledW2, ledb2, out);
}